// round 6
// baseline (speedup 1.0000x reference)
#include <cuda_runtime.h>
#include <cuda_bf16.h>
#include <cstdint>
#include <cstddef>

#define EMB     512
#define HID     512
#define NCLASS  50257
#define BATCH   64
#define STEPS   256
#define GATES   2048                  // 4*HID
#define ROWSXW  (STEPS*BATCH)         // 16384

#define NCTA_REC 64                   // persistent CTAs for recurrence
#define SMEM_REC ((512*33 + 64*520 + 64*33)*4)   // WhT + hs + pre = 209152 B
#define SMEM_OUT (BATCH*HID*4)                   // 131072 B

// ---------------- scratch (device globals: allocation-free) ----------------
__device__ float    g_xw[(size_t)ROWSXW * GATES];   // 128 MB: xw[t*64+b][4H]
__device__ float    g_h[2][BATCH * HID];            // double-buffered hidden state
__device__ unsigned g_bar;                          // grid barrier counter

// ---------------- helpers ----------------
static __device__ __forceinline__ float to_tf32(float x) {
    uint32_t u;
    asm("cvt.rna.tf32.f32 %0, %1;" : "=r"(u) : "f"(x));
    return __uint_as_float(u);
}

// D += A(16x8,row) * B(8x8,col), tf32 in / f32 accum
static __device__ __forceinline__ void mma8(float c[4], const float a[4], const float b[2]) {
    asm volatile(
        "mma.sync.aligned.m16n8k8.row.col.f32.tf32.tf32.f32 "
        "{%0,%1,%2,%3},{%4,%5,%6,%7},{%8,%9},{%0,%1,%2,%3};\n"
        : "+f"(c[0]), "+f"(c[1]), "+f"(c[2]), "+f"(c[3])
        : "r"(__float_as_uint(a[0])), "r"(__float_as_uint(a[1])),
          "r"(__float_as_uint(a[2])), "r"(__float_as_uint(a[3])),
          "r"(__float_as_uint(b[0])), "r"(__float_as_uint(b[1])));
}

static __device__ __forceinline__ float sigf(float x) {
    return 1.0f / (1.0f + __expf(-x));
}
static __device__ __forceinline__ float tanh_fast(float x) {
    float ax = fabsf(x);
    float e  = __expf(-2.0f * ax);          // in (0,1], no overflow
    float r  = (1.0f - e) / (1.0f + e);
    return copysignf(r, x);
}

// ---------------- K0: per-launch init (h0 = 0, barrier = 0) ----------------
__global__ void k_init() {
    int i = blockIdx.x * blockDim.x + threadIdx.x;
    if (i < BATCH * HID) g_h[0][i] = 0.0f;
    if (i == 0) g_bar = 0u;
}

// ---------------- K1: xw[t*64+b][j] = emb[X[b][t]] @ Wi + bi + bh ----------
// GEMM M=16384, N=2048, K=512. CTA tile 128x128, BK=32, tf32 mma.
__global__ __launch_bounds__(256, 2)
void k_xw(const int* __restrict__ X, const float* __restrict__ emb,
          const float* __restrict__ Wi, const float* __restrict__ bi,
          const float* __restrict__ bh) {
    __shared__ float As[128 * 33];
    __shared__ float Bs[32 * 132];
    __shared__ int   tok[128];

    const int tid = threadIdx.x;
    const int cb  = blockIdx.x;   // 0..15 col block
    const int rb  = blockIdx.y;   // 0..127 row block

    if (tid < 128) {
        int r = rb * 128 + tid;                 // r = t*64 + b
        tok[tid] = X[(r & 63) * STEPS + (r >> 6)];
    }

    const int warp = tid >> 5, lane = tid & 31;
    const int g = lane >> 2, tq = lane & 3;
    const int mi0 = (warp & 3) * 2;             // 2 m-tiles (16 rows) per warp
    const int ni0 = (warp >> 2) * 8;            // 8 n-tiles (8 cols) per warp

    float acc[2][8][4];
#pragma unroll
    for (int m = 0; m < 2; m++)
#pragma unroll
        for (int n = 0; n < 8; n++)
#pragma unroll
            for (int q = 0; q < 4; q++) acc[m][n][q] = 0.0f;

    __syncthreads();

    for (int k0 = 0; k0 < EMB; k0 += 32) {
        // A tile: gather 128 emb rows x 32 cols (tf32-convert on store)
#pragma unroll
        for (int idx = tid; idx < 128 * 8; idx += 256) {
            int i = idx >> 3, kq = (idx & 7) * 4;
            float4 v = *(const float4*)(emb + (size_t)tok[i] * EMB + k0 + kq);
            float* d = As + i * 33 + kq;
            d[0] = to_tf32(v.x); d[1] = to_tf32(v.y);
            d[2] = to_tf32(v.z); d[3] = to_tf32(v.w);
        }
        // B tile: Wi[k0..k0+31][cb*128 .. +127]
#pragma unroll
        for (int idx = tid; idx < 32 * 32; idx += 256) {
            int kk = idx >> 5, nq = (idx & 31) * 4;
            float4 v = *(const float4*)(Wi + (size_t)(k0 + kk) * GATES + cb * 128 + nq);
            float* d = Bs + kk * 132 + nq;
            d[0] = to_tf32(v.x); d[1] = to_tf32(v.y);
            d[2] = to_tf32(v.z); d[3] = to_tf32(v.w);
        }
        __syncthreads();

#pragma unroll
        for (int ks = 0; ks < 32; ks += 8) {
            float a[2][4];
#pragma unroll
            for (int m = 0; m < 2; m++) {
                int r0 = (mi0 + m) * 16 + g;
                a[m][0] = As[r0 * 33 + ks + tq];
                a[m][1] = As[(r0 + 8) * 33 + ks + tq];
                a[m][2] = As[r0 * 33 + ks + tq + 4];
                a[m][3] = As[(r0 + 8) * 33 + ks + tq + 4];
            }
#pragma unroll
            for (int n = 0; n < 8; n++) {
                float b[2];
                int c0 = (ni0 + n) * 8 + g;
                b[0] = Bs[(ks + tq) * 132 + c0];
                b[1] = Bs[(ks + tq + 4) * 132 + c0];
                mma8(acc[0][n], a[0], b);
                mma8(acc[1][n], a[1], b);
            }
        }
        __syncthreads();
    }

    // epilogue: += bi + bh, store to g_xw
#pragma unroll
    for (int m = 0; m < 2; m++) {
        int row = rb * 128 + (mi0 + m) * 16 + g;
#pragma unroll
        for (int n = 0; n < 8; n++) {
            int col = cb * 128 + (ni0 + n) * 8 + tq * 2;
            float b0 = bi[col] + bh[col];
            float b1 = bi[col + 1] + bh[col + 1];
            float* o0 = g_xw + (size_t)row * GATES + col;
            o0[0] = acc[m][n][0] + b0;
            o0[1] = acc[m][n][1] + b1;
            float* o1 = g_xw + (size_t)(row + 8) * GATES + col;
            o1[0] = acc[m][n][2] + b0;
            o1[1] = acc[m][n][3] + b1;
        }
    }
}

// ---------------- K2: persistent LSTM recurrence (layer 1 only) ------------
// 64 CTAs, each owns 8 hidden units -> 32 local gate cols [i|f|g|o]x8.
__global__ __launch_bounds__(256, 1)
void k_rec(const float* __restrict__ Wh) {
    extern __shared__ float sm[];
    float* WhT = sm;                         // [512][33] tf32 local Wh slice
    float* hs  = sm + 512 * 33;              // [64][520] staged h (tf32)
    float* pre = sm + 512 * 33 + 64 * 520;   // [64][33]  pre-activations

    const int tid  = threadIdx.x;
    const int warp = tid >> 5, lane = tid & 31;
    const int g = lane >> 2, tq = lane & 3;
    const int baseu = blockIdx.x * 8;        // first owned hidden unit

    // Load local Wh slice: local col c -> global col (c>>3)*512 + baseu + (c&7)
    for (int idx = tid; idx < 512 * 32; idx += 256) {
        int k = idx >> 5, c = idx & 31;
        int gcol = (c >> 3) * HID + baseu + (c & 7);
        WhT[k * 33 + c] = to_tf32(Wh[(size_t)k * GATES + gcol]);
    }

    // MMA tiles: warp -> m-tile mi (16 rows), 2 n-tiles starting at ni0
    const int mi  = warp & 3;
    const int ni0 = (warp >> 2) * 2;
    const int ar0 = mi * 16 + g;

    // elementwise: entries tid and tid+256 -> (b = e>>3, lu = e&7)
    const int b0_ = tid >> 3,         lu0 = tid & 7;
    const int b1_ = (tid + 256) >> 3, lu1 = (tid + 256) & 7;
    float cs0 = 0.0f, cs1 = 0.0f;

    __syncthreads();   // WhT ready

    for (int t = 0; t < STEPS; ++t) {
        // stage h_t into smem (tf32); .cv load: h written by peer SMs
        const float* hsrc = g_h[t & 1];
        for (int idx = tid; idx < 8192; idx += 256) {
            int b = idx >> 7, kq = (idx & 127) * 4;
            float4 v = __ldcv((const float4*)(hsrc + b * HID + kq));
            float4 w;
            w.x = to_tf32(v.x); w.y = to_tf32(v.y);
            w.z = to_tf32(v.z); w.w = to_tf32(v.w);
            *(float4*)(hs + b * 520 + kq) = w;
        }
        __syncthreads();

        // h @ Wh_slice : two 16x8 tiles per warp, K=512
        float acc0[4] = {0, 0, 0, 0}, acc1[4] = {0, 0, 0, 0};
        {
            const float* ha = hs + ar0 * 520 + tq;
            const float* wb = WhT + tq * 33 + ni0 * 8 + g;
#pragma unroll 16
            for (int k = 0; k < HID; k += 8) {
                float a[4];
                a[0] = ha[k];
                a[1] = ha[8 * 520 + k];
                a[2] = ha[k + 4];
                a[3] = ha[8 * 520 + k + 4];
                float bb0[2], bb1[2];
                bb0[0] = wb[k * 33];
                bb0[1] = wb[(k + 4) * 33];
                bb1[0] = wb[k * 33 + 8];
                bb1[1] = wb[(k + 4) * 33 + 8];
                mma8(acc0, a, bb0);
                mma8(acc1, a, bb1);
            }
        }
        // scatter pre-activations to smem
        {
            int col = ni0 * 8 + tq * 2;
            pre[ar0 * 33 + col]           = acc0[0];
            pre[ar0 * 33 + col + 1]       = acc0[1];
            pre[(ar0 + 8) * 33 + col]     = acc0[2];
            pre[(ar0 + 8) * 33 + col + 1] = acc0[3];
            pre[ar0 * 33 + col + 8]       = acc1[0];
            pre[ar0 * 33 + col + 9]       = acc1[1];
            pre[(ar0 + 8) * 33 + col + 8] = acc1[2];
            pre[(ar0 + 8) * 33 + col + 9] = acc1[3];
        }
        __syncthreads();

        // gates + state update (c in registers), write h_{t+1}
        float* hdst = g_h[(t + 1) & 1];
        {
            const size_t xb = ((size_t)t * BATCH + b0_) * GATES + baseu + lu0;
            float pi = pre[b0_ * 33 + lu0]       + g_xw[xb];
            float pf = pre[b0_ * 33 + 8  + lu0]  + g_xw[xb + 512];
            float pg = pre[b0_ * 33 + 16 + lu0]  + g_xw[xb + 1024];
            float po = pre[b0_ * 33 + 24 + lu0]  + g_xw[xb + 1536];
            float ii = sigf(pi), ff = sigf(pf);
            float gg = tanh_fast(pg), oo = sigf(po);
            cs0 = ff * cs0 + ii * gg;
            hdst[b0_ * HID + baseu + lu0] = oo * tanh_fast(cs0);
        }
        {
            const size_t xb = ((size_t)t * BATCH + b1_) * GATES + baseu + lu1;
            float pi = pre[b1_ * 33 + lu1]       + g_xw[xb];
            float pf = pre[b1_ * 33 + 8  + lu1]  + g_xw[xb + 512];
            float pg = pre[b1_ * 33 + 16 + lu1]  + g_xw[xb + 1024];
            float po = pre[b1_ * 33 + 24 + lu1]  + g_xw[xb + 1536];
            float ii = sigf(pi), ff = sigf(pf);
            float gg = tanh_fast(pg), oo = sigf(po);
            cs1 = ff * cs1 + ii * gg;
            hdst[b1_ * HID + baseu + lu1] = oo * tanh_fast(cs1);
        }
        __syncthreads();   // all threads done writing hdst / reading pre

        // grid barrier: monotone counter, one arrive per CTA per step
        if (tid == 0) {
            __threadfence();
            atomicAdd(&g_bar, 1u);
            const unsigned target = (unsigned)(t + 1) * NCTA_REC;
            volatile unsigned* p = &g_bar;
            while (*p < target) { }
        }
        __syncthreads();
    }
}

// ---------------- K3: out[b][n] = h_T[b] . Wout[n] + bout[n] (fp32) --------
__global__ __launch_bounds__(256, 1)
void k_out(const float* __restrict__ Wout, const float* __restrict__ bout,
           float* __restrict__ out) {
    extern __shared__ float sh[];   // [64][512] final h
    for (int i = threadIdx.x; i < BATCH * HID / 4; i += 256)
        ((float4*)sh)[i] = ((const float4*)g_h[0])[i];
    __syncthreads();

    const int lane   = threadIdx.x & 31;
    const int gw     = blockIdx.x * 8 + (threadIdx.x >> 5);
    const int nwarps = gridDim.x * 8;

    for (int n = gw; n < NCLASS; n += nwarps) {
        float acc[64];
#pragma unroll
        for (int b = 0; b < 64; b++) acc[b] = 0.0f;

        const float4* wrow = (const float4*)(Wout + (size_t)n * HID);
#pragma unroll
        for (int c = 0; c < 4; c++) {
            float4 w = wrow[c * 32 + lane];
            int k4 = c * 32 + lane;
#pragma unroll
            for (int b = 0; b < 64; b++) {
                float4 h4 = ((const float4*)sh)[b * 128 + k4];
                acc[b] += h4.x * w.x + h4.y * w.y + h4.z * w.z + h4.w * w.w;
            }
        }
#pragma unroll
        for (int off = 16; off; off >>= 1)
#pragma unroll
            for (int b = 0; b < 64; b++)
                acc[b] += __shfl_xor_sync(0xffffffffu, acc[b], off);

        float bv = bout[n];
        out[(size_t)lane * NCLASS + n]        = acc[lane] + bv;
        out[(size_t)(lane + 32) * NCLASS + n] = acc[lane + 32] + bv;
    }
}

// ---------------- host launcher -------------------------------------------
extern "C" void kernel_launch(void* const* d_in, const int* in_sizes, int n_in,
                              void* d_out, int out_size) {
    (void)in_sizes; (void)n_in; (void)out_size;
    const int*   X    = (const int*)  d_in[0];
    const float* emb  = (const float*)d_in[1];
    const float* Wi   = (const float*)d_in[2];
    const float* Wh   = (const float*)d_in[3];
    const float* bi   = (const float*)d_in[4];
    const float* bh   = (const float*)d_in[5];
    // d_in[6..9] = Wi1, Wh1, bi1, bh1 : dead code in the reference
    const float* Wout = (const float*)d_in[10];
    const float* bout = (const float*)d_in[11];
    float* out = (float*)d_out;

    cudaFuncSetAttribute(k_rec, cudaFuncAttributeMaxDynamicSharedMemorySize, SMEM_REC);
    cudaFuncSetAttribute(k_out, cudaFuncAttributeMaxDynamicSharedMemorySize, SMEM_OUT);

    k_init<<<(BATCH * HID + 255) / 256, 256>>>();

    dim3 gx(GATES / 128, ROWSXW / 128);     // (16, 128)
    k_xw<<<gx, 256>>>(X, emb, Wi, bi, bh);

    k_rec<<<NCTA_REC, 256, SMEM_REC>>>(Wh);

    k_out<<<148, 256, SMEM_OUT>>>(Wout, bout, out);
}

// round 8
// speedup vs baseline: 2.0194x; 2.0194x over previous
#include <cuda_runtime.h>
#include <cuda_bf16.h>
#include <cstdint>
#include <cstddef>

#define EMB     512
#define HID     512
#define NCLASS  50257
#define BATCH   64
#define STEPS   256
#define GATES   2048                  // 4*HID
#define ROWSXW  (STEPS*BATCH)         // 16384

#define NCTA_REC 64                   // persistent CTAs for recurrence
// WhT[512][40] + hs[64][516] + pre[64][40]  (floats)
#define SMEM_REC ((512*40 + 64*516 + 64*40)*4)   // 224256 B

// ---------------- scratch (device globals: allocation-free) ----------------
// xw layout: [t][blk][gate][b*8+lu]  (blk = hidden-unit block of 8, lu = unit in block)
__device__ float          g_xw[(size_t)ROWSXW * GATES];   // 128 MB
__device__ __nv_bfloat16  g_h[2][BATCH * HID];            // double-buffered h (bf16)
__device__ float          g_hfin[BATCH * HID];            // final-step h (fp32)
__device__ unsigned       g_bar;                          // grid barrier counter

// ---------------- helpers ----------------
static __device__ __forceinline__ float to_tf32(float x) {
    uint32_t u;
    asm("cvt.rna.tf32.f32 %0, %1;" : "=r"(u) : "f"(x));
    return __uint_as_float(u);
}

// D += A(16x8,row) * B(8x8,col), tf32 in / f32 accum
static __device__ __forceinline__ void mma8(float c[4], const float a[4], const float b[2]) {
    asm volatile(
        "mma.sync.aligned.m16n8k8.row.col.f32.tf32.tf32.f32 "
        "{%0,%1,%2,%3},{%4,%5,%6,%7},{%8,%9},{%0,%1,%2,%3};\n"
        : "+f"(c[0]), "+f"(c[1]), "+f"(c[2]), "+f"(c[3])
        : "r"(__float_as_uint(a[0])), "r"(__float_as_uint(a[1])),
          "r"(__float_as_uint(a[2])), "r"(__float_as_uint(a[3])),
          "r"(__float_as_uint(b[0])), "r"(__float_as_uint(b[1])));
}

static __device__ __forceinline__ float sigf(float x) {
    return 1.0f / (1.0f + __expf(-x));
}
static __device__ __forceinline__ float tanh_fast(float x) {
    float ax = fabsf(x);
    float e  = __expf(-2.0f * ax);          // in (0,1], no overflow
    float r  = (1.0f - e) / (1.0f + e);
    return copysignf(r, x);
}

// ---------------- K0: per-launch init (h0 = 0 bf16, barrier = 0) -----------
__global__ void k_init() {
    int i = blockIdx.x * blockDim.x + threadIdx.x;   // 128*256 = 32768 threads
    if (i < BATCH * HID) g_h[0][i] = __float2bfloat16(0.0f);
    if (i == 0) g_bar = 0u;
}

// ---------------- K1: xw = emb[X] @ Wi + bi + bh  -> g_xw (rec layout) -----
// GEMM M=16384, N=2048, K=512. CTA tile 128x128, BK=32, tf32 mma.
__global__ __launch_bounds__(256, 2)
void k_xw(const int* __restrict__ X, const float* __restrict__ emb,
          const float* __restrict__ Wi, const float* __restrict__ bi,
          const float* __restrict__ bh) {
    __shared__ float As[128 * 33];
    __shared__ float Bs[32 * 132];
    __shared__ int   tok[128];

    const int tid = threadIdx.x;
    const int cb  = blockIdx.x;   // 0..15 col block
    const int rb  = blockIdx.y;   // 0..127 row block

    if (tid < 128) {
        int r = rb * 128 + tid;                 // r = t*64 + b
        tok[tid] = X[(r & 63) * STEPS + (r >> 6)];
    }

    const int warp = tid >> 5, lane = tid & 31;
    const int g = lane >> 2, tq = lane & 3;
    const int mi0 = (warp & 3) * 2;             // 2 m-tiles (16 rows) per warp
    const int ni0 = (warp >> 2) * 8;            // 8 n-tiles (8 cols) per warp

    float acc[2][8][4];
#pragma unroll
    for (int m = 0; m < 2; m++)
#pragma unroll
        for (int n = 0; n < 8; n++)
#pragma unroll
            for (int q = 0; q < 4; q++) acc[m][n][q] = 0.0f;

    __syncthreads();

    for (int k0 = 0; k0 < EMB; k0 += 32) {
        // A tile: gather 128 emb rows x 32 cols (tf32-convert on store)
#pragma unroll
        for (int idx = tid; idx < 128 * 8; idx += 256) {
            int i = idx >> 3, kq = (idx & 7) * 4;
            float4 v = *(const float4*)(emb + (size_t)tok[i] * EMB + k0 + kq);
            float* d = As + i * 33 + kq;
            d[0] = to_tf32(v.x); d[1] = to_tf32(v.y);
            d[2] = to_tf32(v.z); d[3] = to_tf32(v.w);
        }
        // B tile: Wi[k0..k0+31][cb*128 .. +127]
#pragma unroll
        for (int idx = tid; idx < 32 * 32; idx += 256) {
            int kk = idx >> 5, nq = (idx & 31) * 4;
            float4 v = *(const float4*)(Wi + (size_t)(k0 + kk) * GATES + cb * 128 + nq);
            float* d = Bs + kk * 132 + nq;
            d[0] = to_tf32(v.x); d[1] = to_tf32(v.y);
            d[2] = to_tf32(v.z); d[3] = to_tf32(v.w);
        }
        __syncthreads();

#pragma unroll
        for (int ks = 0; ks < 32; ks += 8) {
            float a[2][4];
#pragma unroll
            for (int m = 0; m < 2; m++) {
                int r0 = (mi0 + m) * 16 + g;
                a[m][0] = As[r0 * 33 + ks + tq];
                a[m][1] = As[(r0 + 8) * 33 + ks + tq];
                a[m][2] = As[r0 * 33 + ks + tq + 4];
                a[m][3] = As[(r0 + 8) * 33 + ks + tq + 4];
            }
#pragma unroll
            for (int n = 0; n < 8; n++) {
                float b[2];
                int c0 = (ni0 + n) * 8 + g;
                b[0] = Bs[(ks + tq) * 132 + c0];
                b[1] = Bs[(ks + tq + 4) * 132 + c0];
                mma8(acc[0][n], a[0], b);
                mma8(acc[1][n], a[1], b);
            }
        }
        __syncthreads();
    }

    // epilogue: += bi + bh, store to g_xw in recurrence-friendly layout:
    //   dest = ((t*64 + blk)*4 + gate)*512 + b*8 + lu
#pragma unroll
    for (int m = 0; m < 2; m++) {
        int row = rb * 128 + (mi0 + m) * 16 + g;   // = t*64 + b  (b = row&63 < 56 here)
        int t = row >> 6, b = row & 63;
#pragma unroll
        for (int n = 0; n < 8; n++) {
            int col = cb * 128 + (ni0 + n) * 8 + tq * 2;   // global gate column
            int gate = col >> 9;
            int blk  = (col >> 3) & 63;
            int lu   = col & 7;                            // in {0,2,4,6}
            float b0 = bi[col] + bh[col];
            float b1 = bi[col + 1] + bh[col + 1];
            size_t d = (((size_t)t * 64 + blk) * 4 + gate) * 512 + b * 8 + lu;
            g_xw[d]     = acc[m][n][0] + b0;
            g_xw[d + 1] = acc[m][n][1] + b1;
            size_t d2 = d + 64;                            // row+8 -> b+8
            g_xw[d2]     = acc[m][n][2] + b0;
            g_xw[d2 + 1] = acc[m][n][3] + b1;
        }
    }
}

// ---------------- K2: persistent LSTM recurrence (layer 1 only) ------------
// 64 CTAs, each owns 8 hidden units -> 32 local gate cols [i|f|g|o]x8.
__global__ __launch_bounds__(256, 1)
void k_rec(const float* __restrict__ Wh) {
    extern __shared__ float sm[];
    float* WhT = sm;                          // [512][40] tf32 local Wh slice
    float* hs  = sm + 512 * 40;               // [64][516] staged h
    float* pre = sm + 512 * 40 + 64 * 516;    // [64][40]  pre-activations

    const int tid  = threadIdx.x;
    const int warp = tid >> 5, lane = tid & 31;
    const int g = lane >> 2, tq = lane & 3;
    const int blk   = blockIdx.x;
    const int baseu = blk * 8;                // first owned hidden unit

    // Load local Wh slice: local col c -> global col (c>>3)*512 + baseu + (c&7)
    for (int idx = tid; idx < 512 * 32; idx += 256) {
        int k = idx >> 5, c = idx & 31;
        int gcol = (c >> 3) * HID + baseu + (c & 7);
        WhT[k * 40 + c] = to_tf32(Wh[(size_t)k * GATES + gcol]);
    }

    // MMA tiles: warp -> m-tile mi (16 rows), 2 n-tiles starting at ni0
    const int mi  = warp & 3;
    const int ni0 = (warp >> 2) * 2;
    const int ar0 = mi * 16 + g;

    // elementwise: entries tid and tid+256 -> (b = e>>3, lu = e&7)
    const int b0_ = tid >> 3,         lu0 = tid & 7;
    const int b1_ = (tid + 256) >> 3, lu1 = (tid + 256) & 7;
    float cs0 = 0.0f, cs1 = 0.0f;

    __syncthreads();   // WhT ready

    for (int t = 0; t < STEPS; ++t) {
        // prefetch this step's xw gates (coalesced, 8 independent LDGs)
        const float* xwb = g_xw + (((size_t)t * 64 + blk) * 4) * 512;
        float xA[4], xB[4];
#pragma unroll
        for (int gt = 0; gt < 4; gt++) {
            xA[gt] = __ldcg(xwb + gt * 512 + tid);
            xB[gt] = __ldcg(xwb + gt * 512 + 256 + tid);
        }

        // stage h_t (bf16 -> fp32) into smem; .cv: written by peer SMs
        const uint4* hsrc = (const uint4*)g_h[t & 1];   // 8 bf16 per uint4
        for (int idx = tid; idx < 4096; idx += 256) {
            int b  = idx >> 6;            // 64 uint4 per batch row
            int kq = (idx & 63) * 8;
            uint4 v = __ldcv(hsrc + idx);
            float2 f0 = __bfloat1622float2(*(const __nv_bfloat162*)&v.x);
            float2 f1 = __bfloat1622float2(*(const __nv_bfloat162*)&v.y);
            float2 f2 = __bfloat1622float2(*(const __nv_bfloat162*)&v.z);
            float2 f3 = __bfloat1622float2(*(const __nv_bfloat162*)&v.w);
            float4 w0 = make_float4(f0.x, f0.y, f1.x, f1.y);
            float4 w1 = make_float4(f2.x, f2.y, f3.x, f3.y);
            *(float4*)(hs + b * 516 + kq)     = w0;
            *(float4*)(hs + b * 516 + kq + 4) = w1;
        }
        __syncthreads();

        // h @ Wh_slice : two 16x8 tiles per warp, K=512 (conflict-free strides)
        float acc0[4] = {0, 0, 0, 0}, acc1[4] = {0, 0, 0, 0};
        {
            const float* ha = hs + ar0 * 516 + tq;
            const float* wb = WhT + tq * 40 + ni0 * 8 + g;
#pragma unroll 16
            for (int k = 0; k < HID; k += 8) {
                float a[4];
                a[0] = ha[k];
                a[1] = ha[8 * 516 + k];
                a[2] = ha[k + 4];
                a[3] = ha[8 * 516 + k + 4];
                float bb0[2], bb1[2];
                bb0[0] = wb[k * 40];
                bb0[1] = wb[(k + 4) * 40];
                bb1[0] = wb[k * 40 + 8];
                bb1[1] = wb[(k + 4) * 40 + 8];
                mma8(acc0, a, bb0);
                mma8(acc1, a, bb1);
            }
        }
        // scatter pre-activations to smem
        {
            int col = ni0 * 8 + tq * 2;
            pre[ar0 * 40 + col]           = acc0[0];
            pre[ar0 * 40 + col + 1]       = acc0[1];
            pre[(ar0 + 8) * 40 + col]     = acc0[2];
            pre[(ar0 + 8) * 40 + col + 1] = acc0[3];
            pre[ar0 * 40 + col + 8]       = acc1[0];
            pre[ar0 * 40 + col + 9]       = acc1[1];
            pre[(ar0 + 8) * 40 + col + 8] = acc1[2];
            pre[(ar0 + 8) * 40 + col + 9] = acc1[3];
        }
        __syncthreads();

        // gates + state update (c in registers), write h_{t+1} (bf16)
        __nv_bfloat16* hdst = g_h[(t + 1) & 1];
        {
            float pi = pre[b0_ * 40 + lu0]      + xA[0];
            float pf = pre[b0_ * 40 + 8  + lu0] + xA[1];
            float pg = pre[b0_ * 40 + 16 + lu0] + xA[2];
            float po = pre[b0_ * 40 + 24 + lu0] + xA[3];
            float ii = sigf(pi), ff = sigf(pf);
            float gg = tanh_fast(pg), oo = sigf(po);
            cs0 = ff * cs0 + ii * gg;
            float hv = oo * tanh_fast(cs0);
            hdst[b0_ * HID + baseu + lu0] = __float2bfloat16(hv);
            if (t == STEPS - 1) g_hfin[b0_ * HID + baseu + lu0] = hv;
        }
        {
            float pi = pre[b1_ * 40 + lu1]      + xB[0];
            float pf = pre[b1_ * 40 + 8  + lu1] + xB[1];
            float pg = pre[b1_ * 40 + 16 + lu1] + xB[2];
            float po = pre[b1_ * 40 + 24 + lu1] + xB[3];
            float ii = sigf(pi), ff = sigf(pf);
            float gg = tanh_fast(pg), oo = sigf(po);
            cs1 = ff * cs1 + ii * gg;
            float hv = oo * tanh_fast(cs1);
            hdst[b1_ * HID + baseu + lu1] = __float2bfloat16(hv);
            if (t == STEPS - 1) g_hfin[b1_ * HID + baseu + lu1] = hv;
        }
        __syncthreads();   // all threads done writing hdst / reading pre

        // grid barrier: monotone counter, one arrive per CTA per step
        if (tid == 0) {
            __threadfence();
            atomicAdd(&g_bar, 1u);
            const unsigned target = (unsigned)(t + 1) * NCTA_REC;
            volatile unsigned* p = &g_bar;
            while (*p < target) { }
        }
        __syncthreads();
    }
}

// ---------------- K3: out[64][NCLASS] = h_fin @ Wout^T + bout (tf32 GEMM) --
// CTA tile 64 x 128, BK=32. 393 CTAs. Memory-bound on the Wout stream.
__global__ __launch_bounds__(256)
void k_out(const float* __restrict__ Wout, const float* __restrict__ bout,
           float* __restrict__ out) {
    __shared__ float As[64 * 36];     // h tile  (stride 36 == 4 mod 32: conflict-free)
    __shared__ float Bs[128 * 40];    // Wout tile, n-major (stride 40 == 8 mod 32)

    const int tid = threadIdx.x;
    const int n0  = blockIdx.x * 128;

    const int warp = tid >> 5, lane = tid & 31;
    const int g = lane >> 2, tq = lane & 3;
    const int mi = warp & 3;           // m-tile: rows mi*16 .. +15
    const int nh = warp >> 2;          // n-half: cols nh*64 .. +63 (8 n-tiles)

    float acc[8][4];
#pragma unroll
    for (int n = 0; n < 8; n++)
#pragma unroll
        for (int q = 0; q < 4; q++) acc[n][q] = 0.0f;

    for (int k0 = 0; k0 < HID; k0 += 32) {
        // A: h rows 64 x 32 k  (512 float4 / 256 thr = 2 each)
#pragma unroll
        for (int idx = tid; idx < 64 * 8; idx += 256) {
            int i = idx >> 3, kq = (idx & 7) * 4;
            float4 v = *(const float4*)(g_hfin + i * HID + k0 + kq);
            float* d = As + i * 36 + kq;
            d[0] = to_tf32(v.x); d[1] = to_tf32(v.y);
            d[2] = to_tf32(v.z); d[3] = to_tf32(v.w);
        }
        // B: Wout rows n0..n0+127 x 32 k (clamp OOB rows; stores guarded later)
#pragma unroll
        for (int idx = tid; idx < 128 * 8; idx += 256) {
            int n = idx >> 3, kq = (idx & 7) * 4;
            int gn = n0 + n; if (gn >= NCLASS) gn = NCLASS - 1;
            float4 v = *(const float4*)(Wout + (size_t)gn * HID + k0 + kq);
            float* d = Bs + n * 40 + kq;
            d[0] = to_tf32(v.x); d[1] = to_tf32(v.y);
            d[2] = to_tf32(v.z); d[3] = to_tf32(v.w);
        }
        __syncthreads();

#pragma unroll
        for (int ks = 0; ks < 32; ks += 8) {
            float a[4];
            int r0 = mi * 16 + g;
            a[0] = As[r0 * 36 + ks + tq];
            a[1] = As[(r0 + 8) * 36 + ks + tq];
            a[2] = As[r0 * 36 + ks + tq + 4];
            a[3] = As[(r0 + 8) * 36 + ks + tq + 4];
#pragma unroll
            for (int n = 0; n < 8; n++) {
                int col = nh * 64 + n * 8 + g;
                float b[2];
                b[0] = Bs[col * 40 + ks + tq];
                b[1] = Bs[col * 40 + ks + tq + 4];
                mma8(acc[n], a, b);
            }
        }
        __syncthreads();
    }

    // epilogue: out[b][n] = acc + bout[n]  (row-major [64][NCLASS])
    int row = mi * 16 + g;
#pragma unroll
    for (int n = 0; n < 8; n++) {
        int cn = n0 + nh * 64 + n * 8 + tq * 2;
        if (cn < NCLASS) {
            float bv = bout[cn];
            out[(size_t)row * NCLASS + cn]       = acc[n][0] + bv;
            out[(size_t)(row + 8) * NCLASS + cn] = acc[n][2] + bv;
        }
        if (cn + 1 < NCLASS) {
            float bv = bout[cn + 1];
            out[(size_t)row * NCLASS + cn + 1]       = acc[n][1] + bv;
            out[(size_t)(row + 8) * NCLASS + cn + 1] = acc[n][3] + bv;
        }
    }
}

// ---------------- host launcher -------------------------------------------
extern "C" void kernel_launch(void* const* d_in, const int* in_sizes, int n_in,
                              void* d_out, int out_size) {
    (void)in_sizes; (void)n_in; (void)out_size;
    const int*   X    = (const int*)  d_in[0];
    const float* emb  = (const float*)d_in[1];
    const float* Wi   = (const float*)d_in[2];
    const float* Wh   = (const float*)d_in[3];
    const float* bi   = (const float*)d_in[4];
    const float* bh   = (const float*)d_in[5];
    // d_in[6..9] = Wi1, Wh1, bi1, bh1 : dead code in the reference
    const float* Wout = (const float*)d_in[10];
    const float* bout = (const float*)d_in[11];
    float* out = (float*)d_out;

    cudaFuncSetAttribute(k_rec, cudaFuncAttributeMaxDynamicSharedMemorySize, SMEM_REC);

    k_init<<<128, 256>>>();

    dim3 gx(GATES / 128, ROWSXW / 128);     // (16, 128)
    k_xw<<<gx, 256>>>(X, emb, Wi, bi, bh);

    k_rec<<<NCTA_REC, 256, SMEM_REC>>>(Wh);

    k_out<<<(NCLASS + 127) / 128, 256>>>(Wout, bout, out);
}